// round 2
// baseline (speedup 1.0000x reference)
#include <cuda_runtime.h>
#include <cstdint>

// Problem constants (fixed shapes for GCN_8967891714538)
#define N_NODES 50000
#define N_EDGES 800000
#define IN_CH   128
#define HID_CH  128
#define OUT_CH  64

#define CHUNK   1024
#define NCHUNKS ((N_NODES + CHUNK - 1) / CHUNK)   // 49

// ---------------- scratch (static device globals; no allocation) -------------
__device__ __align__(16) float g_hs1[(size_t)N_NODES * HID_CH];  // (x @ W1) * dinv[row]
__device__ __align__(16) float g_a1 [(size_t)N_NODES * HID_CH];  // relu(agg1 + b1)
__device__ __align__(16) float g_hs2[(size_t)N_NODES * OUT_CH];  // (a1 @ W2) * dinv[row]
__device__ float g_dinv[N_NODES];
__device__ int   g_ecnt[N_NODES];
__device__ int   g_fill[N_NODES];
__device__ int   g_rowptr[N_NODES + 1];
__device__ int   g_esrc[N_EDGES];
__device__ int   g_csum[NCHUNKS];
__device__ int   g_coff[NCHUNKS];
__device__ int   g_is64;   // 1 if edge_index buffer is int64, 0 if int32

// ---------------- edge_index dtype detection ---------------------------------
// Genuine int64 node ids are in [0, N_NODES). If the buffer is really int32,
// a long-long read packs two random ids (lo | hi<<32) >= 2^32 almost surely.
__global__ void k_detect(const void* __restrict__ ei) {
    if (threadIdx.x == 0 && blockIdx.x == 0) {
        const long long* p = (const long long*)ei;
        int is64 = 1;
        for (int i = 0; i < 64; i++) {           // 512 bytes — safe for both layouts
            long long v = p[i];
            if (v < 0 || v >= (long long)N_NODES) { is64 = 0; break; }
        }
        g_is64 = is64;
    }
}

__device__ __forceinline__ int edge_at(const void* __restrict__ ei, int idx) {
    if (g_is64) return (int)((const long long*)ei)[idx];
    return ((const int*)ei)[idx];
}

// ---------------- CSR build ---------------------------------------------------
__global__ void k_init_nodes() {
    int v = blockIdx.x * blockDim.x + threadIdx.x;
    if (v < N_NODES) { g_ecnt[v] = 0; g_fill[v] = 0; }
}

__global__ void k_count(const void* __restrict__ ei) {
    int e = blockIdx.x * blockDim.x + threadIdx.x;
    if (e < N_EDGES) {
        int d = edge_at(ei, N_EDGES + e);
        atomicAdd(&g_ecnt[d], 1);
    }
}

__global__ void k_chunksum() {
    __shared__ int sdata[256];
    int c = blockIdx.x, t = threadIdx.x;
    int base = c * CHUNK;
    int s = 0;
    for (int i = t; i < CHUNK; i += 256) {
        int v = base + i;
        s += (v < N_NODES) ? g_ecnt[v] : 0;
    }
    sdata[t] = s;
    __syncthreads();
    for (int off = 128; off > 0; off >>= 1) {
        if (t < off) sdata[t] += sdata[t + off];
        __syncthreads();
    }
    if (t == 0) g_csum[c] = sdata[0];
}

__global__ void k_scanroot() {
    if (threadIdx.x == 0) {
        int run = 0;
        for (int i = 0; i < NCHUNKS; i++) { g_coff[i] = run; run += g_csum[i]; }
        g_rowptr[N_NODES] = run;  // == N_EDGES
    }
}

__global__ void k_scanchunk() {
    __shared__ int s[CHUNK];
    int c = blockIdx.x, t = threadIdx.x;
    int v = c * CHUNK + t;
    int x = (v < N_NODES) ? g_ecnt[v] : 0;
    s[t] = x;
    __syncthreads();
    // Hillis-Steele inclusive scan
    for (int off = 1; off < CHUNK; off <<= 1) {
        int val = (t >= off) ? s[t - off] : 0;
        __syncthreads();
        s[t] += val;
        __syncthreads();
    }
    if (v < N_NODES) g_rowptr[v] = g_coff[c] + s[t] - x;  // exclusive
}

__global__ void k_fill(const void* __restrict__ ei) {
    int e = blockIdx.x * blockDim.x + threadIdx.x;
    if (e < N_EDGES) {
        int sN = edge_at(ei, e);
        int d  = edge_at(ei, N_EDGES + e);
        int pos = g_rowptr[d] + atomicAdd(&g_fill[d], 1);
        g_esrc[pos] = sN;
    }
}

__global__ void k_dinv() {
    int v = blockIdx.x * blockDim.x + threadIdx.x;
    if (v < N_NODES) g_dinv[v] = rsqrtf((float)(g_ecnt[v] + 1));  // +1 self-loop
}

// ---------------- GEMM with dinv row-scale epilogue --------------------------
// blockDim.x == C (thread owns one output column); R rows per block.
template<int K, int C>
__device__ __forceinline__ void gemm_body(const float* __restrict__ X,
                                          const float* __restrict__ W,
                                          float* __restrict__ out) {
    constexpr int R = 16;
    const int t    = threadIdx.x;
    const int row0 = blockIdx.x * R;

    float acc[R];
#pragma unroll
    for (int r = 0; r < R; r++) acc[r] = 0.0f;

    for (int k = 0; k < K; k += 4) {
        float w0 = __ldg(&W[(k + 0) * C + t]);
        float w1 = __ldg(&W[(k + 1) * C + t]);
        float w2 = __ldg(&W[(k + 2) * C + t]);
        float w3 = __ldg(&W[(k + 3) * C + t]);
#pragma unroll
        for (int r = 0; r < R; r++) {
            const int row = row0 + r;
            float4 xv = __ldg((const float4*)(X + (size_t)row * K + k));
            acc[r] = fmaf(xv.x, w0, acc[r]);
            acc[r] = fmaf(xv.y, w1, acc[r]);
            acc[r] = fmaf(xv.z, w2, acc[r]);
            acc[r] = fmaf(xv.w, w3, acc[r]);
        }
    }
#pragma unroll
    for (int r = 0; r < R; r++) {
        const int row = row0 + r;
        if (row < N_NODES)
            out[(size_t)row * C + t] = acc[r] * g_dinv[row];
    }
}

__global__ void __launch_bounds__(HID_CH) k_gemm1(const float* __restrict__ X,
                                                  const float* __restrict__ W) {
    gemm_body<IN_CH, HID_CH>(X, W, g_hs1);
}
__global__ void __launch_bounds__(OUT_CH) k_gemm2(const float* __restrict__ W) {
    gemm_body<HID_CH, OUT_CH>(g_a1, W, g_hs2);
}

// ---------------- CSR gather aggregation -------------------------------------
// out[v] = (hs[v] + sum_{s in in(v)} hs[s]) * dinv[v] + bias  [+ relu]
template<int C, bool RELU>
__device__ __forceinline__ void agg_body(const float* __restrict__ hs,
                                         const float* __restrict__ bias,
                                         float* __restrict__ out) {
    constexpr int F4 = C / 4;   // float4 lanes per node row
    int gtid = blockIdx.x * blockDim.x + threadIdx.x;
    int node = gtid / F4;
    int j    = gtid % F4;
    if (node >= N_NODES) return;

    const float4* hv = (const float4*)hs;
    float4 acc = __ldg(&hv[(size_t)node * F4 + j]);   // self-loop term (pre-scaled)

    int beg = g_rowptr[node];
    int end = g_rowptr[node + 1];
    for (int e = beg; e < end; e++) {
        int s = g_esrc[e];
        float4 v = __ldg(&hv[(size_t)s * F4 + j]);
        acc.x += v.x; acc.y += v.y; acc.z += v.z; acc.w += v.w;
    }

    float dv = g_dinv[node];
    float4 b = __ldg(&((const float4*)bias)[j]);
    float4 r;
    r.x = fmaf(acc.x, dv, b.x);
    r.y = fmaf(acc.y, dv, b.y);
    r.z = fmaf(acc.z, dv, b.z);
    r.w = fmaf(acc.w, dv, b.w);
    if (RELU) {
        r.x = fmaxf(r.x, 0.0f); r.y = fmaxf(r.y, 0.0f);
        r.z = fmaxf(r.z, 0.0f); r.w = fmaxf(r.w, 0.0f);
    }
    ((float4*)out)[(size_t)node * F4 + j] = r;
}

__global__ void k_agg1(const float* __restrict__ b1) {
    agg_body<HID_CH, true>(g_hs1, b1, g_a1);
}
__global__ void k_agg2(const float* __restrict__ b2, float* __restrict__ out) {
    agg_body<OUT_CH, false>(g_hs2, b2, out);
}

// ---------------- launch ------------------------------------------------------
extern "C" void kernel_launch(void* const* d_in, const int* in_sizes, int n_in,
                              void* d_out, int out_size) {
    const float* x  = (const float*)d_in[0];
    const void*  ei = d_in[1];
    const float* W1 = (const float*)d_in[2];
    const float* b1 = (const float*)d_in[3];
    const float* W2 = (const float*)d_in[4];
    const float* b2 = (const float*)d_in[5];
    float* out = (float*)d_out;
    (void)in_sizes; (void)n_in; (void)out_size;

    const int TB = 256;

    // Detect edge_index dtype (int64 vs int32), then build CSR + dinv
    k_detect    <<<1, 32>>>(ei);
    k_init_nodes<<<(N_NODES + TB - 1) / TB, TB>>>();
    k_count     <<<(N_EDGES + TB - 1) / TB, TB>>>(ei);
    k_chunksum  <<<NCHUNKS, 256>>>();
    k_scanroot  <<<1, 32>>>();
    k_scanchunk <<<NCHUNKS, CHUNK>>>();
    k_fill      <<<(N_EDGES + TB - 1) / TB, TB>>>(ei);
    k_dinv      <<<(N_NODES + TB - 1) / TB, TB>>>();

    // Layer 1: hs1 = (x @ W1) * dinv ; a1 = relu(gather(hs1)*dinv + b1)
    k_gemm1<<<(N_NODES + 15) / 16, HID_CH>>>(x, W1);
    {
        int total = N_NODES * (HID_CH / 4);
        k_agg1<<<(total + TB - 1) / TB, TB>>>(b1);
    }

    // Layer 2: hs2 = (a1 @ W2) * dinv ; out = gather(hs2)*dinv + b2
    k_gemm2<<<(N_NODES + 15) / 16, OUT_CH>>>(W2);
    {
        int total = N_NODES * (OUT_CH / 4);
        k_agg2<<<(total + TB - 1) / TB, TB>>>(b2, out);
    }
}